// round 15
// baseline (speedup 1.0000x reference)
#include <cuda_runtime.h>
#include <cuda_bf16.h>
#include <math.h>

#define MAXB 1024
#define MAXD 1024
#define NCLS 16
#define MARGIN 0.3f
#define EPSF 1e-8f

// Scratch (static device globals; no dynamic allocation allowed)
__device__ float g_dmat[MAXB * MAXB];
__device__ __nv_bfloat16 g_xhi[MAXB * MAXD];
__device__ __nv_bfloat16 g_xlo[MAXB * MAXD];
__device__ float g_norms[MAXB];
__device__ int   g_labels[MAXB];
__device__ int   g_cls_cnt[NCLS];
__device__ int   g_cls_list[NCLS * MAXB];
__device__ float g_psum[2 * MAXB];
__device__ unsigned int g_pcnt[2 * MAXB];
__device__ int   g_done;   // zero-init; last-block pattern, self-resets

// ---- wrappers ----
__device__ __forceinline__ void ldsm4(unsigned& r0, unsigned& r1,
                                      unsigned& r2, unsigned& r3, unsigned addr) {
    asm volatile("ldmatrix.sync.aligned.m8n8.x4.shared.b16 {%0,%1,%2,%3}, [%4];"
                 : "=r"(r0), "=r"(r1), "=r"(r2), "=r"(r3) : "r"(addr));
}
__device__ __forceinline__ void mma_bf16(float* c, const unsigned* a,
                                         unsigned b0, unsigned b1) {
    asm volatile(
        "mma.sync.aligned.m16n8k16.row.col.f32.bf16.bf16.f32 "
        "{%0,%1,%2,%3}, {%4,%5,%6,%7}, {%8,%9}, {%0,%1,%2,%3};"
        : "+f"(c[0]), "+f"(c[1]), "+f"(c[2]), "+f"(c[3])
        : "r"(a[0]), "r"(a[1]), "r"(a[2]), "r"(a[3]), "r"(b0), "r"(b1));
}
__device__ __forceinline__ unsigned pack_bf16x2(__nv_bfloat16 a, __nv_bfloat16 b) {
    __nv_bfloat162 p = __halves2bfloat162(a, b);
    return *reinterpret_cast<unsigned*>(&p);
}
__device__ __forceinline__ void cp16(unsigned dst, const void* src) {
    asm volatile("cp.async.ca.shared.global [%0], [%1], 16;" :: "r"(dst), "l"(src));
}
__device__ __forceinline__ void cp_commit() {
    asm volatile("cp.async.commit_group;");
}
__device__ __forceinline__ void cp_wait_all() {
    asm volatile("cp.async.wait_group 0;");
}

// ---------------------------------------------------------------------------
// Kernel 0: prep. Roles by bid:
//   [0, convBlocks)           : fp32 -> bf16 hi/lo split (x converted ONCE)
//   [convBlocks, +normBlocks) : row norms, warp per row (deterministic)
//   last                      : builder — labels (int64-vs-int32: odd 32-bit
//                               words among first B all zero => int64) +
//                               per-class member lists via order-preserving
//                               warp ballots.
// ---------------------------------------------------------------------------
__global__ __launch_bounds__(256) void prep_kernel(const float* __restrict__ x,
                                                   const int* __restrict__ raw,
                                                   int B, int D,
                                                   int convBlocks, int normBlocks) {
    int bid = blockIdx.x, tid = threadIdx.x;

    if (bid < convBlocks) {
        size_t g = (size_t)bid * 256 + tid;
        size_t off = g * 8;
        if (off + 8 <= (size_t)B * D) {
            float4 v0 = *(const float4*)(x + off);
            float4 v1 = *(const float4*)(x + off + 4);
            float vv[8] = {v0.x, v0.y, v0.z, v0.w, v1.x, v1.y, v1.z, v1.w};
            __nv_bfloat16 h[8], l[8];
#pragma unroll
            for (int e = 0; e < 8; e++) {
                h[e] = __float2bfloat16(vv[e]);
                l[e] = __float2bfloat16(vv[e] - __bfloat162float(h[e]));
            }
            *(uint4*)(g_xhi + off) = make_uint4(
                pack_bf16x2(h[0], h[1]), pack_bf16x2(h[2], h[3]),
                pack_bf16x2(h[4], h[5]), pack_bf16x2(h[6], h[7]));
            *(uint4*)(g_xlo + off) = make_uint4(
                pack_bf16x2(l[0], l[1]), pack_bf16x2(l[2], l[3]),
                pack_bf16x2(l[4], l[5]), pack_bf16x2(l[6], l[7]));
        }
        return;
    }

    if (bid < convBlocks + normBlocks) {
        int row  = (bid - convBlocks) * 8 + (tid >> 5);
        int lane = tid & 31;
        if (row < B) {
            const float4* xr = (const float4*)(x + (size_t)row * D);
            float s = 0.0f;
            for (int c = lane; c < (D >> 2); c += 32) {
                float4 v = xr[c];
                s += v.x * v.x + v.y * v.y + v.z * v.z + v.w * v.w;
            }
#pragma unroll
            for (int o = 16; o > 0; o >>= 1) s += __shfl_down_sync(0xffffffffu, s, o);
            if (lane == 0) g_norms[row] = s;
        }
        return;
    }

    // ---- builder ----
    __shared__ int slab[MAXB];
    __shared__ int oddnz;
    if (tid == 0) oddnz = 0;
    __syncthreads();
    int loc = 0;
    for (int t = 2 * tid + 1; t < B; t += 512)
        if (raw[t] != 0) loc = 1;
    if (loc) atomicOr(&oddnz, 1);
    __syncthreads();
    bool is64 = (oddnz == 0);
    for (int t = tid; t < B; t += 256) {
        int v = is64 ? raw[2 * t] : raw[t];
        g_labels[t] = v;
        slab[t] = v;
    }
    __syncthreads();
    if (tid < 32) {
        int base[NCLS];
#pragma unroll
        for (int c = 0; c < NCLS; c++) base[c] = 0;
        unsigned lanemask = (1u << tid) - 1u;
        for (int j0 = 0; j0 < B; j0 += 32) {
            int j = j0 + tid;
            int lj = (j < B) ? slab[j] : -1;
#pragma unroll
            for (int c = 0; c < NCLS; c++) {
                unsigned m = __ballot_sync(0xffffffffu, lj == c);
                if (lj == c)
                    g_cls_list[c * MAXB + base[c] + __popc(m & lanemask)] = j;
                base[c] += __popc(m);
            }
        }
        if (tid == 0) {
#pragma unroll
            for (int c = 0; c < NCLS; c++) g_cls_cnt[c] = base[c];
        }
    }
}

// ---------------------------------------------------------------------------
// Kernel 1: Gram + distance matrix via bf16 hi/lo MMA (R13-validated mapping,
// rel_err 3.2e-7), staging PRE-CONVERTED bf16 with cp.async, ONE barrier per
// chunk. Upper-triangle 64x64 tiles, 256 threads, warps 4(m) x 2(n), warp
// tile m16 x n32, dot = hi*hi' + hi*lo' + lo*hi'. Norms from g_norms (fp32).
// Mirror written from smem. The diagonal (only point differing from the
// reference) is never consumed downstream.
// ---------------------------------------------------------------------------
__global__ __launch_bounds__(256) void gram_mma_kernel(int B, int D, int T) {
    __shared__ __align__(16) __nv_bfloat16 Ahi[2][64][24];
    __shared__ __align__(16) __nv_bfloat16 Alo[2][64][24];
    __shared__ __align__(16) __nv_bfloat16 Bhi[2][64][24];
    __shared__ __align__(16) __nv_bfloat16 Blo[2][64][24];
    __shared__ float sT[64][65];
    __shared__ float sNa[64], sNb[64];

    int tid = threadIdx.x;

    int tr = 0, rem = blockIdx.x;
    while (rem >= T - tr) { rem -= T - tr; tr++; }
    int tc = tr + rem;
    int rowBase = tr * 64;
    int colBase = tc * 64;

    // stage norms (visible to all after the prologue barrier below)
    if (tid < 64) {
        int r = rowBase + tid; if (r >= B) r = B - 1;
        sNa[tid] = g_norms[r];
    } else if (tid < 128) {
        int r = colBase + tid - 64; if (r >= B) r = B - 1;
        sNb[tid - 64] = g_norms[r];
    }

    // ---- staging roles: thread -> (row, half, hi/lo) for A and B sides ----
    int srem = tid & 127;
    int srow = srem >> 1;
    int shalf = srem & 1;
    int sm0  = tid >> 7;                  // 0 => hi matrices, 1 => lo matrices
    int garow = rowBase + srow; if (garow >= B) garow = B - 1;
    int gbrow = colBase + srow; if (gbrow >= B) gbrow = B - 1;
    const __nv_bfloat16* srcbase = sm0 ? g_xlo : g_xhi;
    const __nv_bfloat16* srcA = srcbase + (size_t)garow * D + 8 * shalf;
    const __nv_bfloat16* srcB = srcbase + (size_t)gbrow * D + 8 * shalf;
    unsigned uA = (unsigned)__cvta_generic_to_shared(
        sm0 ? &Alo[0][0][0] : &Ahi[0][0][0]) + srow * 48 + shalf * 16;
    unsigned uB = (unsigned)__cvta_generic_to_shared(
        sm0 ? &Blo[0][0][0] : &Bhi[0][0][0]) + srow * 48 + shalf * 16;

    // ---- mma roles (R13-validated verbatim) ----
    int warp = tid >> 5, lane = tid & 31;
    int warp_m = warp & 3, warp_n = warp >> 2;
    const unsigned BUFOFF = 64 * 24 * 2;   // 3072 bytes per buffer

    int arow = 16 * warp_m + (lane & 15);
    int acol = (lane >> 4) << 3;
    unsigned aAhi = (unsigned)__cvta_generic_to_shared(&Ahi[0][arow][acol]);
    unsigned aAlo = (unsigned)__cvta_generic_to_shared(&Alo[0][arow][acol]);
    int bn0 = 32 * warp_n + (lane & 7) + ((lane >> 4) << 3);
    int bk  = ((lane >> 3) & 1) << 3;
    unsigned aBhi0 = (unsigned)__cvta_generic_to_shared(&Bhi[0][bn0][bk]);
    unsigned aBhi1 = (unsigned)__cvta_generic_to_shared(&Bhi[0][bn0 + 16][bk]);
    unsigned aBlo0 = (unsigned)__cvta_generic_to_shared(&Blo[0][bn0][bk]);
    unsigned aBlo1 = (unsigned)__cvta_generic_to_shared(&Blo[0][bn0 + 16][bk]);

    float c[4][4] = {};
    int NCH = D >> 4;

    // prologue: stage chunk 0 into buffer 0
    cp16(uA, srcA);
    cp16(uB, srcB);
    cp_commit();
    cp_wait_all();
    __syncthreads();

    for (int ch = 0; ch < NCH; ch++) {
        int buf = ch & 1;
        // issue next chunk into the other buffer (its last readers passed
        // the barrier at the end of the previous iteration)
        if (ch + 1 < NCH) {
            unsigned nbo = (ch + 1) & 1 ? BUFOFF : 0u;
            int koff = (ch + 1) * 16;
            cp16(uA + nbo, srcA + koff);
            cp16(uB + nbo, srcB + koff);
            cp_commit();
        }

        unsigned bo = buf ? BUFOFF : 0u;
        unsigned ah[4], al[4], bh0[4], bh1[4], bl0[4], bl1[4];
        ldsm4(ah[0], ah[1], ah[2], ah[3], aAhi + bo);
        ldsm4(al[0], al[1], al[2], al[3], aAlo + bo);
        ldsm4(bh0[0], bh0[1], bh0[2], bh0[3], aBhi0 + bo);
        ldsm4(bh1[0], bh1[1], bh1[2], bh1[3], aBhi1 + bo);
        ldsm4(bl0[0], bl0[1], bl0[2], bl0[3], aBlo0 + bo);
        ldsm4(bl1[0], bl1[1], bl1[2], bl1[3], aBlo1 + bo);
        // hi*hi
        mma_bf16(c[0], ah, bh0[0], bh0[1]);
        mma_bf16(c[1], ah, bh0[2], bh0[3]);
        mma_bf16(c[2], ah, bh1[0], bh1[1]);
        mma_bf16(c[3], ah, bh1[2], bh1[3]);
        // hi*lo
        mma_bf16(c[0], ah, bl0[0], bl0[1]);
        mma_bf16(c[1], ah, bl0[2], bl0[3]);
        mma_bf16(c[2], ah, bl1[0], bl1[1]);
        mma_bf16(c[3], ah, bl1[2], bl1[3]);
        // lo*hi
        mma_bf16(c[0], al, bh0[0], bh0[1]);
        mma_bf16(c[1], al, bh0[2], bh0[3]);
        mma_bf16(c[2], al, bh1[0], bh1[1]);
        mma_bf16(c[3], al, bh1[2], bh1[3]);

        if (ch + 1 < NCH) {
            cp_wait_all();
            __syncthreads();
        }
    }

    __syncthreads();   // ensure all warps' mma reads done before sT reuse

    // ---- epilogue (R13-validated mapping) ----
#pragma unroll
    for (int nt = 0; nt < 4; nt++) {
#pragma unroll
        for (int rg = 0; rg < 4; rg++) {
            int row = 16 * warp_m + (lane >> 2) + ((rg >> 1) << 3);
            int col = 32 * warp_n + 8 * nt + 2 * (lane & 3) + (rg & 1);
            float dot = c[nt][rg];
            float t = (sNb[col] - 2.0f * dot) + sNa[row];
            t = fmaxf(t, 0.0f);
            float d = (t > 0.0f) ? sqrtf(t) : 0.0f;
            sT[row][col] = d;
            int gi = rowBase + row, gj = colBase + col;
            if (gi < B && gj < B)
                g_dmat[(size_t)gi * B + gj] = d;
        }
    }

    if (tr != tc) {
        __syncthreads();
        for (int e = tid; e < 4096; e += 256) {
            int jj = e >> 6, ii = e & 63;
            int gi = colBase + jj, gj = rowBase + ii;
            if (gi < B && gj < B)
                g_dmat[(size_t)gi * B + gj] = sT[ii][jj];
        }
    }
}

// ---------------------------------------------------------------------------
// Kernel 2 (R12's measured-best, unchanged): triplet via class lists,
// K-split x2, 160 threads. Count (t>EPS) exact vs reference at these
// magnitudes. Deterministic everywhere. Last block reduces; g_done resets.
// ---------------------------------------------------------------------------
template <int NS>
__global__ __launch_bounds__(160) void triplet_kernel(float* __restrict__ out, int B) {
    __shared__ __align__(16) float sdij[MAXB + 4];
    __shared__ float wsum[5];
    __shared__ unsigned int wcnt[5];
    __shared__ int   is_last;
    __shared__ double fs[5];
    __shared__ unsigned long long fc[5];

    int bid = blockIdx.x;
    int i   = bid >> 1;
    int h   = bid & 1;
    int tid = threadIdx.x;

    int khalf = (B + 1) >> 1;
    int kbeg  = h * khalf;
    int kcnt  = B - kbeg; if (kcnt > khalf) kcnt = khalf;

    const float* drow = g_dmat + (size_t)i * B;
    int li  = g_labels[i];
    int cnt = g_cls_cnt[li];

    float dkr[NS];
    int   lks[NS];
#pragma unroll
    for (int sIdx = 0; sIdx < NS; sIdx++) {
        int k = kbeg + tid + sIdx * 160;
        bool v = (tid + sIdx * 160 < kcnt);
        dkr[sIdx] = v ? drow[k] : 0.0f;
        lks[sIdx] = v ? g_labels[k] : li;
    }

    int npos = cnt - 1;
    for (int t = tid; t < cnt; t += 160) {
        int j = g_cls_list[li * MAXB + t];
        if (j != i) sdij[t - (j > i ? 1 : 0)] = drow[j] + MARGIN;
    }
    if (tid < 4) sdij[npos + tid] = -1e30f;
    __syncthreads();

    float dk[NS];
#pragma unroll
    for (int sIdx = 0; sIdx < NS; sIdx++)
        dk[sIdx] = (lks[sIdx] != li) ? dkr[sIdx] : 1e30f;

    int m4 = (npos + 3) >> 2;
    float sm[NS];
    unsigned cn[NS];
#pragma unroll
    for (int sIdx = 0; sIdx < NS; sIdx++) { sm[sIdx] = 0.0f; cn[sIdx] = 0u; }
    const float4* sd4 = (const float4*)sdij;
    for (int m = 0; m < m4; m++) {
        float4 v = sd4[m];
#pragma unroll
        for (int sIdx = 0; sIdx < NS; sIdx++) {
            float t0 = v.x - dk[sIdx], t1 = v.y - dk[sIdx];
            float t2 = v.z - dk[sIdx], t3 = v.w - dk[sIdx];
            sm[sIdx] += fmaxf(t0, 0.f) + fmaxf(t1, 0.f);
            sm[sIdx] += fmaxf(t2, 0.f) + fmaxf(t3, 0.f);
            cn[sIdx] += (t0 > EPSF); cn[sIdx] += (t1 > EPSF);
            cn[sIdx] += (t2 > EPSF); cn[sIdx] += (t3 > EPSF);
        }
    }

    float s_all = 0.0f;
    unsigned c_all = 0u;
#pragma unroll
    for (int sIdx = 0; sIdx < NS; sIdx++) { s_all += sm[sIdx]; c_all += cn[sIdx]; }

    int lane = tid & 31, w = tid >> 5;
#pragma unroll
    for (int o = 16; o > 0; o >>= 1) {
        s_all += __shfl_down_sync(0xffffffffu, s_all, o);
        c_all += __shfl_down_sync(0xffffffffu, c_all, o);
    }
    if (lane == 0) { wsum[w] = s_all; wcnt[w] = c_all; }
    __syncthreads();
    if (tid == 0) {
        float bs = 0.f; unsigned bc = 0;
#pragma unroll
        for (int q = 0; q < 5; q++) { bs += wsum[q]; bc += wcnt[q]; }
        g_psum[bid] = bs;
        g_pcnt[bid] = bc;
        __threadfence();
        int old = atomicAdd(&g_done, 1);
        is_last = (old == (int)gridDim.x - 1);
    }
    __syncthreads();

    if (is_last) {
        __threadfence();
        int n = gridDim.x;
        double ds = 0.0;
        unsigned long long dc = 0ull;
        for (int t = tid; t < n; t += 160) {
            ds += (double)g_psum[t];
            dc += (unsigned long long)g_pcnt[t];
        }
#pragma unroll
        for (int o = 16; o > 0; o >>= 1) {
            ds += __shfl_down_sync(0xffffffffu, ds, o);
            dc += __shfl_down_sync(0xffffffffu, dc, o);
        }
        if (lane == 0) { fs[w] = ds; fc[w] = dc; }
        __syncthreads();
        if (tid == 0) {
            double ts = 0.0; unsigned long long tc = 0ull;
#pragma unroll
            for (int q = 0; q < 5; q++) { ts += fs[q]; tc += fc[q]; }
            out[0] = (float)(ts / ((double)tc + 1e-8));
            g_done = 0;   // reset for next graph replay
        }
    }
}

// ---------------------------------------------------------------------------
extern "C" void kernel_launch(void* const* d_in, const int* in_sizes, int n_in,
                              void* d_out, int out_size) {
    const float* x   = (const float*)d_in[0];
    const int*   lab = (const int*)d_in[1];   // int32 or int64; detected on device
    float* out = (float*)d_out;

    int B = in_sizes[1];
    int D = in_sizes[0] / B;

    int convBlocks = (B * D + 2047) / 2048;
    int normBlocks = (B + 7) / 8;
    prep_kernel<<<convBlocks + normBlocks + 1, 256>>>(x, lab, B, D,
                                                      convBlocks, normBlocks);

    int T = (B + 63) / 64;
    int ntiles = T * (T + 1) / 2;
    gram_mma_kernel<<<ntiles, 256>>>(B, D, T);

    int khalf = (B + 1) / 2;
    if (khalf <= 320)
        triplet_kernel<2><<<2 * B, 160>>>(out, B);
    else
        triplet_kernel<4><<<2 * B, 160>>>(out, B);
}

// round 16
// speedup vs baseline: 1.1536x; 1.1536x over previous
#include <cuda_runtime.h>
#include <cuda_bf16.h>
#include <math.h>

#define MAXB 1024
#define MAXD 1024
#define NCLS 16
#define MARGIN 0.3f
#define EPSF 1e-8f

// Scratch (static device globals; no dynamic allocation allowed)
__device__ float g_dmat[MAXB * MAXB];
__device__ __nv_bfloat16 g_xhi[MAXB * MAXD];
__device__ __nv_bfloat16 g_xlo[MAXB * MAXD];
__device__ float g_norms[MAXB];
__device__ int   g_labels[MAXB];
__device__ int   g_cls_cnt[NCLS];
__device__ int   g_cls_list[NCLS * MAXB];
__device__ float g_psum[2 * MAXB];
__device__ unsigned int g_pcnt[2 * MAXB];
__device__ int   g_done;   // zero-init; last-block pattern, self-resets

// ---- wrappers ----
__device__ __forceinline__ void ldsm4(unsigned& r0, unsigned& r1,
                                      unsigned& r2, unsigned& r3, unsigned addr) {
    asm volatile("ldmatrix.sync.aligned.m8n8.x4.shared.b16 {%0,%1,%2,%3}, [%4];"
                 : "=r"(r0), "=r"(r1), "=r"(r2), "=r"(r3) : "r"(addr));
}
__device__ __forceinline__ void mma_bf16(float* c, const unsigned* a,
                                         unsigned b0, unsigned b1) {
    asm volatile(
        "mma.sync.aligned.m16n8k16.row.col.f32.bf16.bf16.f32 "
        "{%0,%1,%2,%3}, {%4,%5,%6,%7}, {%8,%9}, {%0,%1,%2,%3};"
        : "+f"(c[0]), "+f"(c[1]), "+f"(c[2]), "+f"(c[3])
        : "r"(a[0]), "r"(a[1]), "r"(a[2]), "r"(a[3]), "r"(b0), "r"(b1));
}
__device__ __forceinline__ unsigned pack_bf16x2(__nv_bfloat16 a, __nv_bfloat16 b) {
    __nv_bfloat162 p = __halves2bfloat162(a, b);
    return *reinterpret_cast<unsigned*>(&p);
}
__device__ __forceinline__ void cp16(unsigned dst, const void* src) {
    asm volatile("cp.async.ca.shared.global [%0], [%1], 16;" :: "r"(dst), "l"(src));
}
__device__ __forceinline__ void cp_commit() {
    asm volatile("cp.async.commit_group;");
}
__device__ __forceinline__ void cp_wait_all() {
    asm volatile("cp.async.wait_group 0;");
}

// ---------------------------------------------------------------------------
// Kernel 0: prep. Roles by bid:
//   [0, convBlocks)           : fp32 -> bf16 hi/lo split (x converted ONCE)
//   [convBlocks, +normBlocks) : row norms, warp per row (deterministic)
//   last                      : builder — labels (int64-vs-int32: odd 32-bit
//                               words among first B all zero => int64) +
//                               per-class member lists, PARALLELIZED: warp w
//                               builds classes {w, w+8} (8x fewer serial
//                               ballots than the old single-warp loop; lists
//                               identical — chunk-order x lane-order).
// ---------------------------------------------------------------------------
__global__ __launch_bounds__(256) void prep_kernel(const float* __restrict__ x,
                                                   const int* __restrict__ raw,
                                                   int B, int D,
                                                   int convBlocks, int normBlocks) {
    int bid = blockIdx.x, tid = threadIdx.x;

    if (bid < convBlocks) {
        size_t g = (size_t)bid * 256 + tid;
        size_t off = g * 8;
        if (off + 8 <= (size_t)B * D) {
            float4 v0 = *(const float4*)(x + off);
            float4 v1 = *(const float4*)(x + off + 4);
            float vv[8] = {v0.x, v0.y, v0.z, v0.w, v1.x, v1.y, v1.z, v1.w};
            __nv_bfloat16 h[8], l[8];
#pragma unroll
            for (int e = 0; e < 8; e++) {
                h[e] = __float2bfloat16(vv[e]);
                l[e] = __float2bfloat16(vv[e] - __bfloat162float(h[e]));
            }
            *(uint4*)(g_xhi + off) = make_uint4(
                pack_bf16x2(h[0], h[1]), pack_bf16x2(h[2], h[3]),
                pack_bf16x2(h[4], h[5]), pack_bf16x2(h[6], h[7]));
            *(uint4*)(g_xlo + off) = make_uint4(
                pack_bf16x2(l[0], l[1]), pack_bf16x2(l[2], l[3]),
                pack_bf16x2(l[4], l[5]), pack_bf16x2(l[6], l[7]));
        }
        return;
    }

    if (bid < convBlocks + normBlocks) {
        int row  = (bid - convBlocks) * 8 + (tid >> 5);
        int lane = tid & 31;
        if (row < B) {
            const float4* xr = (const float4*)(x + (size_t)row * D);
            float s = 0.0f;
            for (int c = lane; c < (D >> 2); c += 32) {
                float4 v = xr[c];
                s += v.x * v.x + v.y * v.y + v.z * v.z + v.w * v.w;
            }
#pragma unroll
            for (int o = 16; o > 0; o >>= 1) s += __shfl_down_sync(0xffffffffu, s, o);
            if (lane == 0) g_norms[row] = s;
        }
        return;
    }

    // ---- builder (parallel across 8 warps) ----
    __shared__ int slab[MAXB];
    __shared__ int oddnz;
    if (tid == 0) oddnz = 0;
    __syncthreads();
    int loc = 0;
    for (int t = 2 * tid + 1; t < B; t += 512)
        if (raw[t] != 0) loc = 1;
    if (loc) atomicOr(&oddnz, 1);
    __syncthreads();
    bool is64 = (oddnz == 0);
    for (int t = tid; t < B; t += 256) {
        int v = is64 ? raw[2 * t] : raw[t];
        g_labels[t] = v;
        slab[t] = v;
    }
    __syncthreads();
    {
        int w8 = tid >> 5, lane8 = tid & 31;
        unsigned lanemask = (1u << lane8) - 1u;
        for (int c = w8; c < NCLS; c += 8) {
            int base = 0;
            for (int j0 = 0; j0 < B; j0 += 32) {
                int j = j0 + lane8;
                int lj = (j < B) ? slab[j] : -1;
                unsigned m = __ballot_sync(0xffffffffu, lj == c);
                if (lj == c)
                    g_cls_list[c * MAXB + base + __popc(m & lanemask)] = j;
                base += __popc(m);
            }
            if (lane8 == 0) g_cls_cnt[c] = base;
        }
    }
}

// ---------------------------------------------------------------------------
// Kernel 1: Gram + distance matrix via bf16 hi/lo MMA (validated mapping,
// rel_err ~4e-7), staging PRE-CONVERTED bf16 with cp.async, ONE barrier per
// chunk. Upper-triangle 64x64 tiles, 256 threads, warps 4(m) x 2(n), warp
// tile m16 x n32. TWO accumulator sets for ILP: c <- hi*hi' then lo*hi'
// (2-deep chain), d2 <- hi*lo' (independent); dot = c + d2 in the epilogue
// (fixed order -> deterministic). Norms from g_norms (fp32). Mirror from
// smem. The diagonal (only point differing from the reference) is never
// consumed downstream.
// ---------------------------------------------------------------------------
__global__ __launch_bounds__(256) void gram_mma_kernel(int B, int D, int T) {
    __shared__ __align__(16) __nv_bfloat16 Ahi[2][64][24];
    __shared__ __align__(16) __nv_bfloat16 Alo[2][64][24];
    __shared__ __align__(16) __nv_bfloat16 Bhi[2][64][24];
    __shared__ __align__(16) __nv_bfloat16 Blo[2][64][24];
    __shared__ float sT[64][65];
    __shared__ float sNa[64], sNb[64];

    int tid = threadIdx.x;

    int tr = 0, rem = blockIdx.x;
    while (rem >= T - tr) { rem -= T - tr; tr++; }
    int tc = tr + rem;
    int rowBase = tr * 64;
    int colBase = tc * 64;

    // stage norms (visible to all after the prologue barrier below)
    if (tid < 64) {
        int r = rowBase + tid; if (r >= B) r = B - 1;
        sNa[tid] = g_norms[r];
    } else if (tid < 128) {
        int r = colBase + tid - 64; if (r >= B) r = B - 1;
        sNb[tid - 64] = g_norms[r];
    }

    // ---- staging roles: thread -> (row, half, hi/lo) for A and B sides ----
    int srem = tid & 127;
    int srow = srem >> 1;
    int shalf = srem & 1;
    int sm0  = tid >> 7;                  // 0 => hi matrices, 1 => lo matrices
    int garow = rowBase + srow; if (garow >= B) garow = B - 1;
    int gbrow = colBase + srow; if (gbrow >= B) gbrow = B - 1;
    const __nv_bfloat16* srcbase = sm0 ? g_xlo : g_xhi;
    const __nv_bfloat16* srcA = srcbase + (size_t)garow * D + 8 * shalf;
    const __nv_bfloat16* srcB = srcbase + (size_t)gbrow * D + 8 * shalf;
    unsigned uA = (unsigned)__cvta_generic_to_shared(
        sm0 ? &Alo[0][0][0] : &Ahi[0][0][0]) + srow * 48 + shalf * 16;
    unsigned uB = (unsigned)__cvta_generic_to_shared(
        sm0 ? &Blo[0][0][0] : &Bhi[0][0][0]) + srow * 48 + shalf * 16;

    // ---- mma roles (validated verbatim) ----
    int warp = tid >> 5, lane = tid & 31;
    int warp_m = warp & 3, warp_n = warp >> 2;
    const unsigned BUFOFF = 64 * 24 * 2;   // 3072 bytes per buffer

    int arow = 16 * warp_m + (lane & 15);
    int acol = (lane >> 4) << 3;
    unsigned aAhi = (unsigned)__cvta_generic_to_shared(&Ahi[0][arow][acol]);
    unsigned aAlo = (unsigned)__cvta_generic_to_shared(&Alo[0][arow][acol]);
    int bn0 = 32 * warp_n + (lane & 7) + ((lane >> 4) << 3);
    int bk  = ((lane >> 3) & 1) << 3;
    unsigned aBhi0 = (unsigned)__cvta_generic_to_shared(&Bhi[0][bn0][bk]);
    unsigned aBhi1 = (unsigned)__cvta_generic_to_shared(&Bhi[0][bn0 + 16][bk]);
    unsigned aBlo0 = (unsigned)__cvta_generic_to_shared(&Blo[0][bn0][bk]);
    unsigned aBlo1 = (unsigned)__cvta_generic_to_shared(&Blo[0][bn0 + 16][bk]);

    float c[4][4] = {};
    float d2[4][4] = {};
    int NCH = D >> 4;

    // prologue: stage chunk 0 into buffer 0
    cp16(uA, srcA);
    cp16(uB, srcB);
    cp_commit();
    cp_wait_all();
    __syncthreads();

    for (int ch = 0; ch < NCH; ch++) {
        int buf = ch & 1;
        // issue next chunk into the other buffer (its last readers passed
        // the barrier at the end of the previous iteration)
        if (ch + 1 < NCH) {
            unsigned nbo = (ch + 1) & 1 ? BUFOFF : 0u;
            int koff = (ch + 1) * 16;
            cp16(uA + nbo, srcA + koff);
            cp16(uB + nbo, srcB + koff);
            cp_commit();
        }

        unsigned bo = buf ? BUFOFF : 0u;
        unsigned ah[4], al[4], bh0[4], bh1[4], bl0[4], bl1[4];
        ldsm4(ah[0], ah[1], ah[2], ah[3], aAhi + bo);
        ldsm4(al[0], al[1], al[2], al[3], aAlo + bo);
        ldsm4(bh0[0], bh0[1], bh0[2], bh0[3], aBhi0 + bo);
        ldsm4(bh1[0], bh1[1], bh1[2], bh1[3], aBhi1 + bo);
        ldsm4(bl0[0], bl0[1], bl0[2], bl0[3], aBlo0 + bo);
        ldsm4(bl1[0], bl1[1], bl1[2], bl1[3], aBlo1 + bo);
        // hi*hi -> c (chain 1 of c)
        mma_bf16(c[0], ah, bh0[0], bh0[1]);
        mma_bf16(c[1], ah, bh0[2], bh0[3]);
        mma_bf16(c[2], ah, bh1[0], bh1[1]);
        mma_bf16(c[3], ah, bh1[2], bh1[3]);
        // hi*lo -> d2 (independent of c)
        mma_bf16(d2[0], ah, bl0[0], bl0[1]);
        mma_bf16(d2[1], ah, bl0[2], bl0[3]);
        mma_bf16(d2[2], ah, bl1[0], bl1[1]);
        mma_bf16(d2[3], ah, bl1[2], bl1[3]);
        // lo*hi -> c (chain 2 of c; overlaps d2 chain)
        mma_bf16(c[0], al, bh0[0], bh0[1]);
        mma_bf16(c[1], al, bh0[2], bh0[3]);
        mma_bf16(c[2], al, bh1[0], bh1[1]);
        mma_bf16(c[3], al, bh1[2], bh1[3]);

        if (ch + 1 < NCH) {
            cp_wait_all();
            __syncthreads();
        }
    }

    __syncthreads();   // ensure all warps' mma reads done before sT reuse

    // ---- epilogue (validated mapping; dot = c + d2, fixed order) ----
#pragma unroll
    for (int nt = 0; nt < 4; nt++) {
#pragma unroll
        for (int rg = 0; rg < 4; rg++) {
            int row = 16 * warp_m + (lane >> 2) + ((rg >> 1) << 3);
            int col = 32 * warp_n + 8 * nt + 2 * (lane & 3) + (rg & 1);
            float dot = c[nt][rg] + d2[nt][rg];
            float t = (sNb[col] - 2.0f * dot) + sNa[row];
            t = fmaxf(t, 0.0f);
            float d = (t > 0.0f) ? sqrtf(t) : 0.0f;
            sT[row][col] = d;
            int gi = rowBase + row, gj = colBase + col;
            if (gi < B && gj < B)
                g_dmat[(size_t)gi * B + gj] = d;
        }
    }

    if (tr != tc) {
        __syncthreads();
        for (int e = tid; e < 4096; e += 256) {
            int jj = e >> 6, ii = e & 63;
            int gi = colBase + jj, gj = rowBase + ii;
            if (gi < B && gj < B)
                g_dmat[(size_t)gi * B + gj] = sT[ii][jj];
        }
    }
}

// ---------------------------------------------------------------------------
// Kernel 2 (R12's measured-best, unchanged): triplet via class lists,
// K-split x2, 160 threads. Count (t>EPS) exact vs reference at these
// magnitudes. Deterministic everywhere. Last block reduces; g_done resets.
// ---------------------------------------------------------------------------
template <int NS>
__global__ __launch_bounds__(160) void triplet_kernel(float* __restrict__ out, int B) {
    __shared__ __align__(16) float sdij[MAXB + 4];
    __shared__ float wsum[5];
    __shared__ unsigned int wcnt[5];
    __shared__ int   is_last;
    __shared__ double fs[5];
    __shared__ unsigned long long fc[5];

    int bid = blockIdx.x;
    int i   = bid >> 1;
    int h   = bid & 1;
    int tid = threadIdx.x;

    int khalf = (B + 1) >> 1;
    int kbeg  = h * khalf;
    int kcnt  = B - kbeg; if (kcnt > khalf) kcnt = khalf;

    const float* drow = g_dmat + (size_t)i * B;
    int li  = g_labels[i];
    int cnt = g_cls_cnt[li];

    float dkr[NS];
    int   lks[NS];
#pragma unroll
    for (int sIdx = 0; sIdx < NS; sIdx++) {
        int k = kbeg + tid + sIdx * 160;
        bool v = (tid + sIdx * 160 < kcnt);
        dkr[sIdx] = v ? drow[k] : 0.0f;
        lks[sIdx] = v ? g_labels[k] : li;
    }

    int npos = cnt - 1;
    for (int t = tid; t < cnt; t += 160) {
        int j = g_cls_list[li * MAXB + t];
        if (j != i) sdij[t - (j > i ? 1 : 0)] = drow[j] + MARGIN;
    }
    if (tid < 4) sdij[npos + tid] = -1e30f;
    __syncthreads();

    float dk[NS];
#pragma unroll
    for (int sIdx = 0; sIdx < NS; sIdx++)
        dk[sIdx] = (lks[sIdx] != li) ? dkr[sIdx] : 1e30f;

    int m4 = (npos + 3) >> 2;
    float sm[NS];
    unsigned cn[NS];
#pragma unroll
    for (int sIdx = 0; sIdx < NS; sIdx++) { sm[sIdx] = 0.0f; cn[sIdx] = 0u; }
    const float4* sd4 = (const float4*)sdij;
    for (int m = 0; m < m4; m++) {
        float4 v = sd4[m];
#pragma unroll
        for (int sIdx = 0; sIdx < NS; sIdx++) {
            float t0 = v.x - dk[sIdx], t1 = v.y - dk[sIdx];
            float t2 = v.z - dk[sIdx], t3 = v.w - dk[sIdx];
            sm[sIdx] += fmaxf(t0, 0.f) + fmaxf(t1, 0.f);
            sm[sIdx] += fmaxf(t2, 0.f) + fmaxf(t3, 0.f);
            cn[sIdx] += (t0 > EPSF); cn[sIdx] += (t1 > EPSF);
            cn[sIdx] += (t2 > EPSF); cn[sIdx] += (t3 > EPSF);
        }
    }

    float s_all = 0.0f;
    unsigned c_all = 0u;
#pragma unroll
    for (int sIdx = 0; sIdx < NS; sIdx++) { s_all += sm[sIdx]; c_all += cn[sIdx]; }

    int lane = tid & 31, w = tid >> 5;
#pragma unroll
    for (int o = 16; o > 0; o >>= 1) {
        s_all += __shfl_down_sync(0xffffffffu, s_all, o);
        c_all += __shfl_down_sync(0xffffffffu, c_all, o);
    }
    if (lane == 0) { wsum[w] = s_all; wcnt[w] = c_all; }
    __syncthreads();
    if (tid == 0) {
        float bs = 0.f; unsigned bc = 0;
#pragma unroll
        for (int q = 0; q < 5; q++) { bs += wsum[q]; bc += wcnt[q]; }
        g_psum[bid] = bs;
        g_pcnt[bid] = bc;
        __threadfence();
        int old = atomicAdd(&g_done, 1);
        is_last = (old == (int)gridDim.x - 1);
    }
    __syncthreads();

    if (is_last) {
        __threadfence();
        int n = gridDim.x;
        double ds = 0.0;
        unsigned long long dc = 0ull;
        for (int t = tid; t < n; t += 160) {
            ds += (double)g_psum[t];
            dc += (unsigned long long)g_pcnt[t];
        }
#pragma unroll
        for (int o = 16; o > 0; o >>= 1) {
            ds += __shfl_down_sync(0xffffffffu, ds, o);
            dc += __shfl_down_sync(0xffffffffu, dc, o);
        }
        if (lane == 0) { fs[w] = ds; fc[w] = dc; }
        __syncthreads();
        if (tid == 0) {
            double ts = 0.0; unsigned long long tc = 0ull;
#pragma unroll
            for (int q = 0; q < 5; q++) { ts += fs[q]; tc += fc[q]; }
            out[0] = (float)(ts / ((double)tc + 1e-8));
            g_done = 0;   // reset for next graph replay
        }
    }
}

// ---------------------------------------------------------------------------
extern "C" void kernel_launch(void* const* d_in, const int* in_sizes, int n_in,
                              void* d_out, int out_size) {
    const float* x   = (const float*)d_in[0];
    const int*   lab = (const int*)d_in[1];   // int32 or int64; detected on device
    float* out = (float*)d_out;

    int B = in_sizes[1];
    int D = in_sizes[0] / B;

    int convBlocks = (B * D + 2047) / 2048;
    int normBlocks = (B + 7) / 8;
    prep_kernel<<<convBlocks + normBlocks + 1, 256>>>(x, lab, B, D,
                                                      convBlocks, normBlocks);

    int T = (B + 63) / 64;
    int ntiles = T * (T + 1) / 2;
    gram_mma_kernel<<<ntiles, 256>>>(B, D, T);

    int khalf = (B + 1) / 2;
    if (khalf <= 320)
        triplet_kernel<2><<<2 * B, 160>>>(out, B);
    else
        triplet_kernel<4><<<2 * B, 160>>>(out, B);
}

// round 17
// speedup vs baseline: 1.1896x; 1.0313x over previous
#include <cuda_runtime.h>
#include <cuda_bf16.h>
#include <math.h>

#define MAXB 1024
#define MAXD 1024
#define NCLS 16
#define MARGIN 0.3f
#define EPSF 1e-8f

// Scratch (static device globals; no dynamic allocation allowed)
__device__ float g_dmat[MAXB * MAXB];
__device__ __nv_bfloat16 g_xhi[MAXB * MAXD];
__device__ __nv_bfloat16 g_xlo[MAXB * MAXD];
__device__ float g_norms[MAXB];
__device__ int   g_labels[MAXB];
__device__ int   g_cls_cnt[NCLS];
__device__ int   g_cls_list[NCLS * MAXB];
__device__ float g_psum[2 * MAXB];
__device__ unsigned int g_pcnt[2 * MAXB];
__device__ int   g_conv_done;   // zero-init; reset by triplet's last block
__device__ int   g_done;        // zero-init; reset by triplet's last block

// ---- wrappers ----
__device__ __forceinline__ int ld_acquire(const int* p) {
    int v;
    asm volatile("ld.global.acquire.gpu.b32 %0, [%1];" : "=r"(v) : "l"(p));
    return v;
}
__device__ __forceinline__ void ldsm4(unsigned& r0, unsigned& r1,
                                      unsigned& r2, unsigned& r3, unsigned addr) {
    asm volatile("ldmatrix.sync.aligned.m8n8.x4.shared.b16 {%0,%1,%2,%3}, [%4];"
                 : "=r"(r0), "=r"(r1), "=r"(r2), "=r"(r3) : "r"(addr));
}
__device__ __forceinline__ void mma_bf16(float* c, const unsigned* a,
                                         unsigned b0, unsigned b1) {
    asm volatile(
        "mma.sync.aligned.m16n8k16.row.col.f32.bf16.bf16.f32 "
        "{%0,%1,%2,%3}, {%4,%5,%6,%7}, {%8,%9}, {%0,%1,%2,%3};"
        : "+f"(c[0]), "+f"(c[1]), "+f"(c[2]), "+f"(c[3])
        : "r"(a[0]), "r"(a[1]), "r"(a[2]), "r"(a[3]), "r"(b0), "r"(b1));
}
__device__ __forceinline__ unsigned pack_bf16x2(__nv_bfloat16 a, __nv_bfloat16 b) {
    __nv_bfloat162 p = __halves2bfloat162(a, b);
    return *reinterpret_cast<unsigned*>(&p);
}
__device__ __forceinline__ void cp16(unsigned dst, const void* src) {
    asm volatile("cp.async.ca.shared.global [%0], [%1], 16;" :: "r"(dst), "l"(src));
}
__device__ __forceinline__ void cp_commit() {
    asm volatile("cp.async.commit_group;");
}
__device__ __forceinline__ void cp_wait_all() {
    asm volatile("cp.async.wait_group 0;");
}

// ---------------------------------------------------------------------------
// Kernel A: fused prep + gram. Roles by bid:
//   [0, convBlocks)      : fp32 -> bf16 hi/lo split; if D==512 also row norms
//                          (each block owns exactly 4 rows; 2 warps per row,
//                          shuffle + fixed-order combine -> deterministic).
//                          Arrives on g_conv_done.
//   [convBlocks, +normB) : generic norm blocks (only launched when D != 512).
//                          Arrive on g_conv_done.
//   next                 : builder — labels (int64-vs-int32: odd 32-bit words
//                          among first B all zero => int64) + per-class lists,
//                          warp w builds classes {w, w+8} (order-preserving).
//   rest                 : gram 64x64 upper-triangle tiles. tid0 spins
//                          (acquire + nanosleep) until g_conv_done ==
//                          convBlocks+normB, then runs the validated bf16
//                          hi/lo MMA (rel_err ~1e-7). All blocks co-resident
//                          (216 blocks, ~33KB smem => 6/SM) -> gate is
//                          deadlock-free and costs ~zero issue.
// ---------------------------------------------------------------------------
__global__ __launch_bounds__(256) void fused_gram_kernel(
    const float* __restrict__ x, const int* __restrict__ raw,
    int B, int D, int T, int convBlocks, int normBlocks)
{
    __shared__ __align__(16) __nv_bfloat16 Ahi[2][64][24];
    __shared__ __align__(16) __nv_bfloat16 Alo[2][64][24];
    __shared__ __align__(16) __nv_bfloat16 Bhi[2][64][24];
    __shared__ __align__(16) __nv_bfloat16 Blo[2][64][24];
    __shared__ float sT[64][65];
    __shared__ float sNa[64], sNb[64];
    __shared__ float swn[8];
    __shared__ int   slab[MAXB];
    __shared__ int   oddnz;

    int bid = blockIdx.x, tid = threadIdx.x;
    int gate = convBlocks + normBlocks;

    // ================= conv blocks =================
    if (bid < convBlocks) {
        size_t off = ((size_t)bid * 256 + tid) * 8;
        float nloc = 0.0f;
        if (off + 8 <= (size_t)B * D) {
            float4 v0 = *(const float4*)(x + off);
            float4 v1 = *(const float4*)(x + off + 4);
            float vv[8] = {v0.x, v0.y, v0.z, v0.w, v1.x, v1.y, v1.z, v1.w};
            __nv_bfloat16 h[8], l[8];
#pragma unroll
            for (int e = 0; e < 8; e++) {
                h[e] = __float2bfloat16(vv[e]);
                l[e] = __float2bfloat16(vv[e] - __bfloat162float(h[e]));
                nloc = fmaf(vv[e], vv[e], nloc);
            }
            *(uint4*)(g_xhi + off) = make_uint4(
                pack_bf16x2(h[0], h[1]), pack_bf16x2(h[2], h[3]),
                pack_bf16x2(h[4], h[5]), pack_bf16x2(h[6], h[7]));
            *(uint4*)(g_xlo + off) = make_uint4(
                pack_bf16x2(l[0], l[1]), pack_bf16x2(l[2], l[3]),
                pack_bf16x2(l[4], l[5]), pack_bf16x2(l[6], l[7]));
        }
        if (D == 512) {
            // 4 rows per block; warp w = (row w>>1, half w&1)
            int w = tid >> 5;
#pragma unroll
            for (int o = 16; o > 0; o >>= 1)
                nloc += __shfl_down_sync(0xffffffffu, nloc, o);
            if ((tid & 31) == 0) swn[w] = nloc;
            __syncthreads();
            if (tid < 4) {
                int row = bid * 4 + tid;
                if (row < B) g_norms[row] = swn[2 * tid] + swn[2 * tid + 1];
            }
        }
        __threadfence();
        __syncthreads();
        if (tid == 0) atomicAdd(&g_conv_done, 1);
        return;
    }

    // ================= generic norm blocks (D != 512 only) =================
    if (bid < gate) {
        int row  = (bid - convBlocks) * 8 + (tid >> 5);
        int lane = tid & 31;
        if (row < B) {
            const float4* xr = (const float4*)(x + (size_t)row * D);
            float s = 0.0f;
            for (int c = lane; c < (D >> 2); c += 32) {
                float4 v = xr[c];
                s += v.x * v.x + v.y * v.y + v.z * v.z + v.w * v.w;
            }
#pragma unroll
            for (int o = 16; o > 0; o >>= 1) s += __shfl_down_sync(0xffffffffu, s, o);
            if (lane == 0) g_norms[row] = s;
        }
        __threadfence();
        __syncthreads();
        if (tid == 0) atomicAdd(&g_conv_done, 1);
        return;
    }

    // ================= builder block =================
    if (bid == gate) {
        if (tid == 0) oddnz = 0;
        __syncthreads();
        int loc = 0;
        for (int t = 2 * tid + 1; t < B; t += 512)
            if (raw[t] != 0) loc = 1;
        if (loc) atomicOr(&oddnz, 1);
        __syncthreads();
        bool is64 = (oddnz == 0);
        for (int t = tid; t < B; t += 256) {
            int v = is64 ? raw[2 * t] : raw[t];
            g_labels[t] = v;
            slab[t] = v;
        }
        __syncthreads();
        int w8 = tid >> 5, lane8 = tid & 31;
        unsigned lanemask = (1u << lane8) - 1u;
        for (int c = w8; c < NCLS; c += 8) {
            int base = 0;
            for (int j0 = 0; j0 < B; j0 += 32) {
                int j = j0 + lane8;
                int lj = (j < B) ? slab[j] : -1;
                unsigned m = __ballot_sync(0xffffffffu, lj == c);
                if (lj == c)
                    g_cls_list[c * MAXB + base + __popc(m & lanemask)] = j;
                base += __popc(m);
            }
            if (lane8 == 0) g_cls_cnt[c] = base;
        }
        return;
    }

    // ================= gram tile blocks =================
    // gate: wait for conversion + norms
    if (tid == 0) {
        while (ld_acquire(&g_conv_done) < gate) __nanosleep(64);
    }
    __syncthreads();

    int tile = bid - gate - 1;
    int tr = 0, rem = tile;
    while (rem >= T - tr) { rem -= T - tr; tr++; }
    int tc = tr + rem;
    int rowBase = tr * 64;
    int colBase = tc * 64;

    // stage norms (after the gate)
    if (tid < 64) {
        int r = rowBase + tid; if (r >= B) r = B - 1;
        sNa[tid] = g_norms[r];
    } else if (tid < 128) {
        int r = colBase + tid - 64; if (r >= B) r = B - 1;
        sNb[tid - 64] = g_norms[r];
    }

    // ---- staging roles: thread -> (row, half, hi/lo) for A and B sides ----
    int srem = tid & 127;
    int srow = srem >> 1;
    int shalf = srem & 1;
    int sm0  = tid >> 7;                  // 0 => hi matrices, 1 => lo matrices
    int garow = rowBase + srow; if (garow >= B) garow = B - 1;
    int gbrow = colBase + srow; if (gbrow >= B) gbrow = B - 1;
    const __nv_bfloat16* srcbase = sm0 ? g_xlo : g_xhi;
    const __nv_bfloat16* srcA = srcbase + (size_t)garow * D + 8 * shalf;
    const __nv_bfloat16* srcB = srcbase + (size_t)gbrow * D + 8 * shalf;
    unsigned uA = (unsigned)__cvta_generic_to_shared(
        sm0 ? &Alo[0][0][0] : &Ahi[0][0][0]) + srow * 48 + shalf * 16;
    unsigned uB = (unsigned)__cvta_generic_to_shared(
        sm0 ? &Blo[0][0][0] : &Bhi[0][0][0]) + srow * 48 + shalf * 16;

    // ---- mma roles (validated verbatim) ----
    int warp = tid >> 5, lane = tid & 31;
    int warp_m = warp & 3, warp_n = warp >> 2;
    const unsigned BUFOFF = 64 * 24 * 2;   // 3072 bytes per buffer

    int arow = 16 * warp_m + (lane & 15);
    int acol = (lane >> 4) << 3;
    unsigned aAhi = (unsigned)__cvta_generic_to_shared(&Ahi[0][arow][acol]);
    unsigned aAlo = (unsigned)__cvta_generic_to_shared(&Alo[0][arow][acol]);
    int bn0 = 32 * warp_n + (lane & 7) + ((lane >> 4) << 3);
    int bk  = ((lane >> 3) & 1) << 3;
    unsigned aBhi0 = (unsigned)__cvta_generic_to_shared(&Bhi[0][bn0][bk]);
    unsigned aBhi1 = (unsigned)__cvta_generic_to_shared(&Bhi[0][bn0 + 16][bk]);
    unsigned aBlo0 = (unsigned)__cvta_generic_to_shared(&Blo[0][bn0][bk]);
    unsigned aBlo1 = (unsigned)__cvta_generic_to_shared(&Blo[0][bn0 + 16][bk]);

    float c[4][4] = {};
    float d2[4][4] = {};
    int NCH = D >> 4;

    // prologue: stage chunk 0 into buffer 0
    cp16(uA, srcA);
    cp16(uB, srcB);
    cp_commit();
    cp_wait_all();
    __syncthreads();

    for (int ch = 0; ch < NCH; ch++) {
        int buf = ch & 1;
        if (ch + 1 < NCH) {
            unsigned nbo = (ch + 1) & 1 ? BUFOFF : 0u;
            int koff = (ch + 1) * 16;
            cp16(uA + nbo, srcA + koff);
            cp16(uB + nbo, srcB + koff);
            cp_commit();
        }

        unsigned bo = buf ? BUFOFF : 0u;
        unsigned ah[4], al[4], bh0[4], bh1[4], bl0[4], bl1[4];
        ldsm4(ah[0], ah[1], ah[2], ah[3], aAhi + bo);
        ldsm4(al[0], al[1], al[2], al[3], aAlo + bo);
        ldsm4(bh0[0], bh0[1], bh0[2], bh0[3], aBhi0 + bo);
        ldsm4(bh1[0], bh1[1], bh1[2], bh1[3], aBhi1 + bo);
        ldsm4(bl0[0], bl0[1], bl0[2], bl0[3], aBlo0 + bo);
        ldsm4(bl1[0], bl1[1], bl1[2], bl1[3], aBlo1 + bo);
        // hi*hi -> c
        mma_bf16(c[0], ah, bh0[0], bh0[1]);
        mma_bf16(c[1], ah, bh0[2], bh0[3]);
        mma_bf16(c[2], ah, bh1[0], bh1[1]);
        mma_bf16(c[3], ah, bh1[2], bh1[3]);
        // hi*lo -> d2 (independent chain)
        mma_bf16(d2[0], ah, bl0[0], bl0[1]);
        mma_bf16(d2[1], ah, bl0[2], bl0[3]);
        mma_bf16(d2[2], ah, bl1[0], bl1[1]);
        mma_bf16(d2[3], ah, bl1[2], bl1[3]);
        // lo*hi -> c
        mma_bf16(c[0], al, bh0[0], bh0[1]);
        mma_bf16(c[1], al, bh0[2], bh0[3]);
        mma_bf16(c[2], al, bh1[0], bh1[1]);
        mma_bf16(c[3], al, bh1[2], bh1[3]);

        if (ch + 1 < NCH) {
            cp_wait_all();
            __syncthreads();
        }
    }

    __syncthreads();

    // ---- epilogue (validated mapping; dot = c + d2, fixed order) ----
#pragma unroll
    for (int nt = 0; nt < 4; nt++) {
#pragma unroll
        for (int rg = 0; rg < 4; rg++) {
            int row = 16 * warp_m + (lane >> 2) + ((rg >> 1) << 3);
            int col = 32 * warp_n + 8 * nt + 2 * (lane & 3) + (rg & 1);
            float dot = c[nt][rg] + d2[nt][rg];
            float t = (sNb[col] - 2.0f * dot) + sNa[row];
            t = fmaxf(t, 0.0f);
            float d = (t > 0.0f) ? sqrtf(t) : 0.0f;
            sT[row][col] = d;
            int gi = rowBase + row, gj = colBase + col;
            if (gi < B && gj < B)
                g_dmat[(size_t)gi * B + gj] = d;
        }
    }

    if (tr != tc) {
        __syncthreads();
        for (int e = tid; e < 4096; e += 256) {
            int jj = e >> 6, ii = e & 63;
            int gi = colBase + jj, gj = rowBase + ii;
            if (gi < B && gj < B)
                g_dmat[(size_t)gi * B + gj] = sT[ii][jj];
        }
    }
}

// ---------------------------------------------------------------------------
// Kernel B (R12's measured-best, unchanged logic): triplet via class lists,
// K-split x2, 160 threads. Count (t>EPS) exact vs reference at these
// magnitudes. Deterministic everywhere. Last block reduces; resets g_done
// AND g_conv_done for the next graph replay.
// ---------------------------------------------------------------------------
template <int NS>
__global__ __launch_bounds__(160) void triplet_kernel(float* __restrict__ out, int B) {
    __shared__ __align__(16) float sdij[MAXB + 4];
    __shared__ float wsum[5];
    __shared__ unsigned int wcnt[5];
    __shared__ int   is_last;
    __shared__ double fs[5];
    __shared__ unsigned long long fc[5];

    int bid = blockIdx.x;
    int i   = bid >> 1;
    int h   = bid & 1;
    int tid = threadIdx.x;

    int khalf = (B + 1) >> 1;
    int kbeg  = h * khalf;
    int kcnt  = B - kbeg; if (kcnt > khalf) kcnt = khalf;

    const float* drow = g_dmat + (size_t)i * B;
    int li  = g_labels[i];
    int cnt = g_cls_cnt[li];

    float dkr[NS];
    int   lks[NS];
#pragma unroll
    for (int sIdx = 0; sIdx < NS; sIdx++) {
        int k = kbeg + tid + sIdx * 160;
        bool v = (tid + sIdx * 160 < kcnt);
        dkr[sIdx] = v ? drow[k] : 0.0f;
        lks[sIdx] = v ? g_labels[k] : li;
    }

    int npos = cnt - 1;
    for (int t = tid; t < cnt; t += 160) {
        int j = g_cls_list[li * MAXB + t];
        if (j != i) sdij[t - (j > i ? 1 : 0)] = drow[j] + MARGIN;
    }
    if (tid < 4) sdij[npos + tid] = -1e30f;
    __syncthreads();

    float dk[NS];
#pragma unroll
    for (int sIdx = 0; sIdx < NS; sIdx++)
        dk[sIdx] = (lks[sIdx] != li) ? dkr[sIdx] : 1e30f;

    int m4 = (npos + 3) >> 2;
    float sm[NS];
    unsigned cn[NS];
#pragma unroll
    for (int sIdx = 0; sIdx < NS; sIdx++) { sm[sIdx] = 0.0f; cn[sIdx] = 0u; }
    const float4* sd4 = (const float4*)sdij;
    for (int m = 0; m < m4; m++) {
        float4 v = sd4[m];
#pragma unroll
        for (int sIdx = 0; sIdx < NS; sIdx++) {
            float t0 = v.x - dk[sIdx], t1 = v.y - dk[sIdx];
            float t2 = v.z - dk[sIdx], t3 = v.w - dk[sIdx];
            sm[sIdx] += fmaxf(t0, 0.f) + fmaxf(t1, 0.f);
            sm[sIdx] += fmaxf(t2, 0.f) + fmaxf(t3, 0.f);
            cn[sIdx] += (t0 > EPSF); cn[sIdx] += (t1 > EPSF);
            cn[sIdx] += (t2 > EPSF); cn[sIdx] += (t3 > EPSF);
        }
    }

    float s_all = 0.0f;
    unsigned c_all = 0u;
#pragma unroll
    for (int sIdx = 0; sIdx < NS; sIdx++) { s_all += sm[sIdx]; c_all += cn[sIdx]; }

    int lane = tid & 31, w = tid >> 5;
#pragma unroll
    for (int o = 16; o > 0; o >>= 1) {
        s_all += __shfl_down_sync(0xffffffffu, s_all, o);
        c_all += __shfl_down_sync(0xffffffffu, c_all, o);
    }
    if (lane == 0) { wsum[w] = s_all; wcnt[w] = c_all; }
    __syncthreads();
    if (tid == 0) {
        float bs = 0.f; unsigned bc = 0;
#pragma unroll
        for (int q = 0; q < 5; q++) { bs += wsum[q]; bc += wcnt[q]; }
        g_psum[bid] = bs;
        g_pcnt[bid] = bc;
        __threadfence();
        int old = atomicAdd(&g_done, 1);
        is_last = (old == (int)gridDim.x - 1);
    }
    __syncthreads();

    if (is_last) {
        __threadfence();
        int n = gridDim.x;
        double ds = 0.0;
        unsigned long long dc = 0ull;
        for (int t = tid; t < n; t += 160) {
            ds += (double)g_psum[t];
            dc += (unsigned long long)g_pcnt[t];
        }
#pragma unroll
        for (int o = 16; o > 0; o >>= 1) {
            ds += __shfl_down_sync(0xffffffffu, ds, o);
            dc += __shfl_down_sync(0xffffffffu, dc, o);
        }
        if (lane == 0) { fs[w] = ds; fc[w] = dc; }
        __syncthreads();
        if (tid == 0) {
            double ts = 0.0; unsigned long long tc = 0ull;
#pragma unroll
            for (int q = 0; q < 5; q++) { ts += fs[q]; tc += fc[q]; }
            out[0] = (float)(ts / ((double)tc + 1e-8));
            g_done = 0;        // reset for next graph replay
            g_conv_done = 0;   // reset the kernel-A gate too
        }
    }
}

// ---------------------------------------------------------------------------
extern "C" void kernel_launch(void* const* d_in, const int* in_sizes, int n_in,
                              void* d_out, int out_size) {
    const float* x   = (const float*)d_in[0];
    const int*   lab = (const int*)d_in[1];   // int32 or int64; detected on device
    float* out = (float*)d_out;

    int B = in_sizes[1];
    int D = in_sizes[0] / B;

    int convBlocks = (B * D + 2047) / 2048;
    int normBlocks = (D == 512) ? 0 : (B + 7) / 8;   // norms fused into conv when D==512
    int T = (B + 63) / 64;
    int ntiles = T * (T + 1) / 2;

    int grid = convBlocks + normBlocks + 1 + ntiles;
    fused_gram_kernel<<<grid, 256>>>(x, lab, B, D, T, convBlocks, normBlocks);

    int khalf = (B + 1) / 2;
    if (khalf <= 320)
        triplet_kernel<2><<<2 * B, 160>>>(out, B);
    else
        triplet_kernel<4><<<2 * B, 160>>>(out, B);
}